// round 15
// baseline (speedup 1.0000x reference)
#include <cuda_runtime.h>
#include <cuda_bf16.h>

// ---------------------------------------------------------------------------
// AdaptiveSystem: 2-expert CNN MoE.
// setup (1 kernel): relayout x->xp, h1 guard rows, gap zero, tables,
//     w1 (tf32) / w2 (bf16 hi+lo split) fragment prep.
// conv1 (3->64)  : mma.sync tf32 m16n8k8, K=32 (27+5 pad).
// conv2 (64->128): mma.sync bf16 m16n8k16, A = w_hi+w_lo bf16 split,
//     B = single-bf16 activations; warp = 32oc x 56px; fused GAP.
//     R15: packed gather geometry + launch_bounds(128,5) for 20 warps/SM.
// gate: softmax-max <= 0.9  <=>  |l0-l1| <= ln(9)
// ---------------------------------------------------------------------------

#define NB 64
#define CH_STRIDE 12882                 // h1: 113 * 114
#define IMG_STRIDE ((size_t)64 * CH_STRIDE)
#define EXPP ((size_t)NB * IMG_STRIDE)

#define XCH_STRIDE 50850                // xp: 225 * 226
#define XIMG_STRIDE (3 * XCH_STRIDE)

#define WFRAG_PER_EXPERT (18 * 2 * 8 * 32 * 8)   // bf16 frags
#define W1FRAG_PER_EXPERT (4 * 4 * 32 * 4)
#define GUARD_ROW_TOTAL (2 * NB * 64 * 114)

// setup kernel block ranges
#define SU_A 14400
#define SU_B (SU_A + 3648)
#define SU_C (SU_B + 64)
#define SU_D (SU_C + 3)
#define SU_E (SU_D + 4)
#define SU_F (SU_E + 72)

__device__ float g_h1[2 * EXPP];
__device__ float g_xp[(size_t)NB * XIMG_STRIDE];
__device__ __align__(16) float g_w2f[2 * WFRAG_PER_EXPERT];
__device__ __align__(16) float g_w1f[2 * W1FRAG_PER_EXPERT];
__device__ unsigned g_imoff[576];
__device__ unsigned g_xoff[32];
__device__ float g_gap[2 * NB * 128];

__device__ __forceinline__ unsigned f2tf(float v) {
    unsigned r;
    asm("cvt.rna.tf32.f32 %0, %1;" : "=r"(r) : "f"(v));
    return r;
}

__device__ __forceinline__ unsigned pack_bf16x2(float lo, float hi) {
    unsigned r;
    asm("cvt.rn.bf16x2.f32 %0, %1, %2;" : "=r"(r) : "f"(hi), "f"(lo));
    return r;
}

__device__ __forceinline__ void mma_tf32(float* c, const unsigned* a,
                                         const unsigned* b) {
    asm volatile(
        "mma.sync.aligned.m16n8k8.row.col.f32.tf32.tf32.f32 "
        "{%0,%1,%2,%3}, {%4,%5,%6,%7}, {%8,%9}, {%0,%1,%2,%3};"
        : "+f"(c[0]), "+f"(c[1]), "+f"(c[2]), "+f"(c[3])
        : "r"(a[0]), "r"(a[1]), "r"(a[2]), "r"(a[3]),
          "r"(b[0]), "r"(b[1]));
}

__device__ __forceinline__ void mma_bf16(float* c, const unsigned* a,
                                         const unsigned* b) {
    asm volatile(
        "mma.sync.aligned.m16n8k16.row.col.f32.bf16.bf16.f32 "
        "{%0,%1,%2,%3}, {%4,%5,%6,%7}, {%8,%9}, {%0,%1,%2,%3};"
        : "+f"(c[0]), "+f"(c[1]), "+f"(c[2]), "+f"(c[3])
        : "r"(a[0]), "r"(a[1]), "r"(a[2]), "r"(a[3]),
          "r"(b[0]), "r"(b[1]));
}

// ---------------------------------------------------------------------------
// setup: all preprocessing in one launch.  grid SU_F blocks x 256.
// ---------------------------------------------------------------------------
__global__ void __launch_bounds__(256) setup_kernel(
    const float* __restrict__ x,
    const float* __restrict__ t_w1, const float* __restrict__ f_w1,
    const float* __restrict__ t_w2, const float* __restrict__ f_w2)
{
    int blk = blockIdx.x;
    int tid = threadIdx.x;

    if (blk < SU_A) {
        int img = blk / 225, row = blk - img * 225;
        int col = tid;
        if (col < 224) {
            #pragma unroll
            for (int c = 0; c < 3; c++) {
                size_t base = (size_t)img * XIMG_STRIDE + c * XCH_STRIDE
                            + row * 226;
                if (row == 224) {
                    g_xp[base + col] = 0.f;
                    if (col < 2) g_xp[base + 224 + col] = 0.f;
                } else {
                    g_xp[base + (col & 1) * 113 + (col >> 1)] =
                        x[((img * 3 + c) * 224 + row) * 224 + col];
                    if (col >= 222)
                        g_xp[base + (col & 1) * 113 + 112] = 0.f;
                }
            }
        }
    } else if (blk < SU_B) {
        int i = (blk - SU_A) * 256 + tid;
        if (i < GUARD_ROW_TOTAL) {
            int ch = i / 114, slot = i % 114;
            g_h1[(size_t)ch * CH_STRIDE + 112 * 114 + slot] = 0.f;
        }
    } else if (blk < SU_C) {
        int i = (blk - SU_B) * 256 + tid;
        if (i < 2 * NB * 128) g_gap[i] = 0.f;
    } else if (blk < SU_D) {
        int i = (blk - SU_C) * 256 + tid;
        if (i < 576) {
            int ch = i / 9, t9 = i % 9, r = t9 / 3, s = t9 % 3;
            g_imoff[i] = ch * CH_STRIDE + r * 114 + (s & 1) * 57 + (s >> 1);
        }
        if (i >= 576 && i < 608) {
            int k = i - 576;
            if (k < 27) {
                int ch = k / 9, t9 = k % 9, r = t9 / 3, s = t9 % 3;
                g_xoff[k] = ch * XCH_STRIDE + r * 226 + (s & 1) * 113 + (s >> 1);
            } else {
                g_xoff[k] = 0;
            }
        }
    } else if (blk < SU_E) {
        int idx = (blk - SU_D) * 256 + tid;
        if (idx < 2 * 4 * 4 * 32) {
            int lane = idx & 31;
            int t = idx >> 5;
            int tile = t & 3;  t >>= 2;
            int ks = t & 3;    t >>= 2;
            int expert = t;
            const float* w = expert ? f_w1 : t_w1;
            int g = lane >> 2, tig = lane & 3;
            int oc0 = tile * 16 + g;
            int k0 = ks * 8 + tig;
            float a = (k0     < 27) ? w[oc0 * 27 + k0]           : 0.f;
            float b = (k0     < 27) ? w[(oc0 + 8) * 27 + k0]     : 0.f;
            float cc = (k0 + 4 < 27) ? w[oc0 * 27 + k0 + 4]      : 0.f;
            float d = (k0 + 4 < 27) ? w[(oc0 + 8) * 27 + k0 + 4] : 0.f;
            float4 hv = make_float4(
                __uint_as_float(f2tf(a)), __uint_as_float(f2tf(b)),
                __uint_as_float(f2tf(cc)), __uint_as_float(f2tf(d)));
            *(float4*)&g_w1f[(size_t)idx * 4] = hv;
        }
    } else {
        int idx = (blk - SU_E) * 256 + tid;
        if (idx < 2 * 18 * 2 * 8 * 32) {
            int lane = idx & 31;
            int t = idx >> 5;
            int tile = t & 7;  t >>= 3;
            int s = t & 1;     t >>= 1;
            int q = t % 18;
            int expert = t / 18;
            const float* w = expert ? f_w2 : t_w2;
            int g = lane >> 2, tig = lane & 3;
            int r0 = tile * 16 + g, r1 = r0 + 8;
            int kb = q * 32 + s * 16 + tig * 2;

            float wv[4][2] = {
                { w[r0 * 576 + kb],     w[r0 * 576 + kb + 1] },
                { w[r1 * 576 + kb],     w[r1 * 576 + kb + 1] },
                { w[r0 * 576 + kb + 8], w[r0 * 576 + kb + 9] },
                { w[r1 * 576 + kb + 8], w[r1 * 576 + kb + 9] } };

            unsigned ah[4], al[4];
            #pragma unroll
            for (int a4 = 0; a4 < 4; a4++) {
                float h0 = __bfloat162float(__float2bfloat16_rn(wv[a4][0]));
                float h1 = __bfloat162float(__float2bfloat16_rn(wv[a4][1]));
                ah[a4] = pack_bf16x2(h0, h1);
                al[a4] = pack_bf16x2(wv[a4][0] - h0, wv[a4][1] - h1);
            }
            float* dst = &g_w2f[(size_t)expert * WFRAG_PER_EXPERT
                                + (size_t)(idx % (18 * 2 * 8 * 32)) * 8];
            *(float4*)dst = make_float4(
                __uint_as_float(ah[0]), __uint_as_float(ah[1]),
                __uint_as_float(ah[2]), __uint_as_float(ah[3]));
            *(float4*)(dst + 4) = make_float4(
                __uint_as_float(al[0]), __uint_as_float(al[1]),
                __uint_as_float(al[2]), __uint_as_float(al[3]));
        }
    }
}

// ---------------------------------------------------------------------------
// conv1 via mma.sync tf32 (R13 winner, unchanged).
// grid: (112 rows, 64 images, 2 experts), block 128.
// ---------------------------------------------------------------------------
#define PADX 120

__global__ void __launch_bounds__(128, 4) conv1_mma_kernel(
    const float* __restrict__ t_b1, const float* __restrict__ f_b1)
{
    __shared__ __align__(16) float smem[64 * 114];
    float2* sB = (float2*)smem;

    int tid = threadIdx.x;
    int wid = tid >> 5, lane = tid & 31;
    int g = lane >> 2, tig = lane & 3;
    int warpM = wid >> 1, warpN = wid & 1;

    int expert = blockIdx.z;
    int img = blockIdx.y;
    int y = blockIdx.x;

    const float* rbase = g_xp + (size_t)img * XIMG_STRIDE + (size_t)y * 452;
    const float* wfrag = g_w1f + (size_t)expert * W1FRAG_PER_EXPERT + lane * 4;
    const float* bs = expert ? f_b1 : t_b1;

    #pragma unroll
    for (int j = 0; j < 14; j++) {
        int i = j * 128 + tid;
        int pair = i / 112, px = i - pair * 112;
        int k0 = (pair >> 2) * 8 + (pair & 3);
        unsigned e0 = __ldg(&g_xoff[k0]);
        unsigned e1 = __ldg(&g_xoff[k0 + 4]);
        float v0 = rbase[e0 + px];
        float v1 = rbase[e1 + px];
        sB[pair * PADX + px] = make_float2(__uint_as_float(f2tf(v0)),
                                           __uint_as_float(f2tf(v1)));
    }
    __syncthreads();

    float acc[2][7][4];
    #pragma unroll
    for (int mt = 0; mt < 2; mt++)
        #pragma unroll
        for (int nt = 0; nt < 7; nt++)
            #pragma unroll
            for (int i = 0; i < 4; i++) acc[mt][nt][i] = 0.f;

    #pragma unroll
    for (int ks = 0; ks < 4; ks++) {
        float2 bp[7];
        #pragma unroll
        for (int nt = 0; nt < 7; nt++)
            bp[nt] = sB[(ks * 4 + tig) * PADX + warpN * 56 + nt * 8 + g];
        #pragma unroll
        for (int mt = 0; mt < 2; mt++) {
            float4 hv = __ldg((const float4*)(wfrag
                        + (size_t)((ks * 4) + warpM * 2 + mt) * 128));
            unsigned ah[4] = {__float_as_uint(hv.x), __float_as_uint(hv.y),
                              __float_as_uint(hv.z), __float_as_uint(hv.w)};
            #pragma unroll
            for (int nt = 0; nt < 7; nt++) {
                unsigned bfr[2] = {__float_as_uint(bp[nt].x),
                                   __float_as_uint(bp[nt].y)};
                mma_tf32(acc[mt][nt], ah, bfr);
            }
        }
    }
    __syncthreads();

    #pragma unroll
    for (int mt = 0; mt < 2; mt++) {
        int oc0 = warpM * 32 + mt * 16 + g;
        float bv0 = __ldg(&bs[oc0]);
        float bv1 = __ldg(&bs[oc0 + 8]);
        #pragma unroll
        for (int nt = 0; nt < 7; nt++) {
            int px0 = warpN * 56 + nt * 8 + tig * 2;
            int idx = px0 >> 1;
            smem[oc0 * 114 + idx]            = fmaxf(acc[mt][nt][0] + bv0, 0.f);
            smem[oc0 * 114 + 57 + idx]       = fmaxf(acc[mt][nt][1] + bv0, 0.f);
            smem[(oc0 + 8) * 114 + idx]      = fmaxf(acc[mt][nt][2] + bv1, 0.f);
            smem[(oc0 + 8) * 114 + 57 + idx] = fmaxf(acc[mt][nt][3] + bv1, 0.f);
        }
    }
    __syncthreads();

    float2* sD = (float2*)smem;
    float2* h1o2 = (float2*)(g_h1 + expert * EXPP + (size_t)img * IMG_STRIDE
                             + (size_t)y * 114);
    int oc = (tid >= 114) ? 2 : (tid >= 57 ? 1 : 0);
    int c2 = tid - oc * 57;
    #pragma unroll 4
    for (int it = 0; it < 28; it++) {
        float2 v = sD[oc * 57 + c2];
        if (c2 == 28) v.x = 0.f;
        if (c2 == 56) v.y = 0.f;
        h1o2[oc * 6441 + c2] = v;
        c2 += 14; oc += 2;
        if (c2 >= 57) { c2 -= 57; oc++; }
    }
    if (tid < 64) {
        float2 v = sD[oc * 57 + c2];
        if (c2 == 28) v.x = 0.f;
        if (c2 == 56) v.y = 0.f;
        h1o2[oc * 6441 + c2] = v;
    }
}

// ---------------------------------------------------------------------------
// conv2 via mma.sync bf16 m16n8k16 (R14 math; R15: packed geometry + occ 5).
// grid: (56 rows, 64 images, 2 experts), block 128.
// ---------------------------------------------------------------------------
#define PADB 72

__global__ void __launch_bounds__(128, 5) conv2_mma_kernel(
    const float* __restrict__ t_b2, const float* __restrict__ f_b2)
{
    __shared__ unsigned sBu[2][16 * PADB];

    int tid = threadIdx.x;
    int wid = tid >> 5, lane = tid & 31;
    int g = lane >> 2, tig = lane & 3;

    int expert = blockIdx.z;
    int img = blockIdx.y;
    int y = blockIdx.x;

    const float* rbase = g_h1 + expert * EXPP + (size_t)img * IMG_STRIDE
                       + (size_t)y * 228;
    const float* wfrag = g_w2f + (size_t)expert * WFRAG_PER_EXPERT
                       + (size_t)(wid * 2) * 256 + lane * 8;
    const float* bs = expert ? f_b2 : t_b2;

    float acc[2][7][4];
    #pragma unroll
    for (int mt = 0; mt < 2; mt++)
        #pragma unroll
        for (int nt = 0; nt < 7; nt++)
            #pragma unroll
            for (int i = 0; i < 4; i++) acc[mt][nt][i] = 0.f;

    // packed gather geometry: geom[j] = (kp << 16) | px
    unsigned geom[7];
    #pragma unroll
    for (int j = 0; j < 7; j++) {
        int w = j * 128 + tid;
        int kp = w / 56, px = w - kp * 56;
        geom[j] = ((unsigned)kp << 16) | (unsigned)px;
    }

    float v0[7], v1[7];
    auto load_chunk = [&](int kb) {
        #pragma unroll
        for (int j = 0; j < 7; j++) {
            int kp = geom[j] >> 16, px = geom[j] & 0xFFFF;
            unsigned e0 = __ldg(&g_imoff[kb + kp * 2]);
            unsigned e1 = __ldg(&g_imoff[kb + kp * 2 + 1]);
            v0[j] = rbase[e0 + px];
            v1[j] = rbase[e1 + px];
        }
    };

    load_chunk(0);

    for (int q = 0; q < 18; q++) {
        int buf = q & 1;
        #pragma unroll
        for (int j = 0; j < 7; j++) {
            int kp = geom[j] >> 16, px = geom[j] & 0xFFFF;
            sBu[buf][kp * PADB + px] = pack_bf16x2(v0[j], v1[j]);
        }
        __syncthreads();
        if (q < 17) load_chunk((q + 1) * 32);

        const float* ap = wfrag + (size_t)q * 4096;
        #pragma unroll
        for (int s = 0; s < 2; s++) {
            unsigned ah[2][4], al[2][4];
            #pragma unroll
            for (int mt = 0; mt < 2; mt++) {
                float4 hv = __ldg((const float4*)(ap + s * 2048 + mt * 256));
                float4 lv = __ldg((const float4*)(ap + s * 2048 + mt * 256 + 4));
                ah[mt][0] = __float_as_uint(hv.x); ah[mt][1] = __float_as_uint(hv.y);
                ah[mt][2] = __float_as_uint(hv.z); ah[mt][3] = __float_as_uint(hv.w);
                al[mt][0] = __float_as_uint(lv.x); al[mt][1] = __float_as_uint(lv.y);
                al[mt][2] = __float_as_uint(lv.z); al[mt][3] = __float_as_uint(lv.w);
            }
            const unsigned* rb0 = &sBu[buf][(s * 8 + tig) * PADB];
            const unsigned* rb1 = rb0 + 4 * PADB;
            #pragma unroll
            for (int nt = 0; nt < 7; nt++) {
                int px = nt * 8 + g;
                unsigned bb[2] = { rb0[px], rb1[px] };
                #pragma unroll
                for (int mt = 0; mt < 2; mt++) {
                    mma_bf16(acc[mt][nt], ah[mt], bb);
                    mma_bf16(acc[mt][nt], al[mt], bb);
                }
            }
        }
    }

    float* gap = &g_gap[expert * (NB * 128) + img * 128];
    #pragma unroll
    for (int mt = 0; mt < 2; mt++) {
        int oc0 = wid * 32 + mt * 16 + g;
        float bv0 = __ldg(&bs[oc0]);
        float bv1 = __ldg(&bs[oc0 + 8]);
        float s0 = 0.f, s1 = 0.f;
        #pragma unroll
        for (int nt = 0; nt < 7; nt++) {
            s0 += fmaxf(acc[mt][nt][0] + bv0, 0.f) + fmaxf(acc[mt][nt][1] + bv0, 0.f);
            s1 += fmaxf(acc[mt][nt][2] + bv1, 0.f) + fmaxf(acc[mt][nt][3] + bv1, 0.f);
        }
        s0 += __shfl_xor_sync(0xffffffffu, s0, 1);
        s0 += __shfl_xor_sync(0xffffffffu, s0, 2);
        s1 += __shfl_xor_sync(0xffffffffu, s1, 1);
        s1 += __shfl_xor_sync(0xffffffffu, s1, 2);
        if (tig == 0) {
            atomicAdd(&gap[oc0], s0);
            atomicAdd(&gap[oc0 + 8], s1);
        }
    }
}

// ---------------------------------------------------------------------------
// final: 512 threads; thread (b, octet) sums 16 k each, shuffle-reduce.
// ---------------------------------------------------------------------------
__global__ void final_kernel(const float* __restrict__ t_wf,
                             const float* __restrict__ t_bf,
                             const float* __restrict__ f_wf,
                             const float* __restrict__ f_bf,
                             float* __restrict__ out)
{
    __shared__ int cnt[NB];
    int t = threadIdx.x;
    int b = t >> 3, oc = t & 7;

    float tl0 = 0.f, tl1 = 0.f, fl0 = 0.f, fl1 = 0.f;
    const float inv = 1.0f / 3136.0f;
    #pragma unroll
    for (int kk = 0; kk < 16; kk++) {
        int k = oc * 16 + kk;
        float gt = g_gap[b * 128 + k] * inv;
        float gf = g_gap[NB * 128 + b * 128 + k] * inv;
        tl0 = fmaf(gt, t_wf[2 * k], tl0);
        tl1 = fmaf(gt, t_wf[2 * k + 1], tl1);
        fl0 = fmaf(gf, f_wf[2 * k], fl0);
        fl1 = fmaf(gf, f_wf[2 * k + 1], fl1);
    }
    #pragma unroll
    for (int off = 1; off <= 4; off <<= 1) {
        tl0 += __shfl_xor_sync(0xffffffffu, tl0, off);
        tl1 += __shfl_xor_sync(0xffffffffu, tl1, off);
        fl0 += __shfl_xor_sync(0xffffffffu, fl0, off);
        fl1 += __shfl_xor_sync(0xffffffffu, fl1, off);
    }
    if (oc == 0) {
        tl0 += t_bf[0]; tl1 += t_bf[1];
        fl0 += f_bf[0]; fl1 += f_bf[1];
        int m = (fabsf(tl0 - tl1) <= 2.1972245773362196f) ? 1 : 0;
        out[2 * b]     = m ? (0.7f * tl0 + 0.3f * fl0) : tl0;
        out[2 * b + 1] = m ? (0.7f * tl1 + 0.3f * fl1) : tl1;
        cnt[b] = m;
    }
    __syncthreads();
    if (t == 0) {
        int c = 0;
        for (int i = 0; i < NB; i++) c += cnt[i];
        out[128] = (float)c / (float)NB;
    }
}

extern "C" void kernel_launch(void* const* d_in, const int* in_sizes, int n_in,
                              void* d_out, int out_size)
{
    const float* x    = (const float*)d_in[0];
    const float* t_w1 = (const float*)d_in[1];
    const float* t_b1 = (const float*)d_in[2];
    const float* t_w2 = (const float*)d_in[3];
    const float* t_b2 = (const float*)d_in[4];
    const float* t_wf = (const float*)d_in[5];
    const float* t_bf = (const float*)d_in[6];
    const float* f_w1 = (const float*)d_in[7];
    const float* f_b1 = (const float*)d_in[8];
    const float* f_w2 = (const float*)d_in[9];
    const float* f_b2 = (const float*)d_in[10];
    const float* f_wf = (const float*)d_in[11];
    const float* f_bf = (const float*)d_in[12];
    float* out = (float*)d_out;

    setup_kernel<<<SU_F, 256>>>(x, t_w1, f_w1, t_w2, f_w2);
    conv1_mma_kernel<<<dim3(112, 64, 2), 128>>>(t_b1, f_b1);
    conv2_mma_kernel<<<dim3(56, 64, 2), 128>>>(t_b2, f_b2);
    final_kernel<<<1, 512>>>(t_wf, t_bf, f_wf, f_bf, out);
}

// round 16
// speedup vs baseline: 1.2588x; 1.2588x over previous
#include <cuda_runtime.h>
#include <cuda_bf16.h>

// ---------------------------------------------------------------------------
// AdaptiveSystem: 2-expert CNN MoE.
// setup (1 kernel): relayout x->xp, h1 guard rows, gap zero, tables,
//     w1 (tf32) / w2 (bf16 hi+lo split) fragment prep.
// conv1 (3->64)  : mma.sync tf32 m16n8k8, K=32 (27+5 pad).
// conv2 (64->128): mma.sync bf16 m16n8k16, A = w_hi+w_lo bf16 split,
//     B = single-bf16 activations; warp = 32oc x 56px; fused GAP.
//     R16: revert to launch_bounds(128,4) — the occ-5 cap spilled (R15).
// gate: softmax-max <= 0.9  <=>  |l0-l1| <= ln(9)
// ---------------------------------------------------------------------------

#define NB 64
#define CH_STRIDE 12882                 // h1: 113 * 114
#define IMG_STRIDE ((size_t)64 * CH_STRIDE)
#define EXPP ((size_t)NB * IMG_STRIDE)

#define XCH_STRIDE 50850                // xp: 225 * 226
#define XIMG_STRIDE (3 * XCH_STRIDE)

#define WFRAG_PER_EXPERT (18 * 2 * 8 * 32 * 8)   // bf16 frags
#define W1FRAG_PER_EXPERT (4 * 4 * 32 * 4)
#define GUARD_ROW_TOTAL (2 * NB * 64 * 114)

// setup kernel block ranges
#define SU_A 14400
#define SU_B (SU_A + 3648)
#define SU_C (SU_B + 64)
#define SU_D (SU_C + 3)
#define SU_E (SU_D + 4)
#define SU_F (SU_E + 72)

__device__ float g_h1[2 * EXPP];
__device__ float g_xp[(size_t)NB * XIMG_STRIDE];
__device__ __align__(16) float g_w2f[2 * WFRAG_PER_EXPERT];
__device__ __align__(16) float g_w1f[2 * W1FRAG_PER_EXPERT];
__device__ unsigned g_imoff[576];
__device__ unsigned g_xoff[32];
__device__ float g_gap[2 * NB * 128];

__device__ __forceinline__ unsigned f2tf(float v) {
    unsigned r;
    asm("cvt.rna.tf32.f32 %0, %1;" : "=r"(r) : "f"(v));
    return r;
}

__device__ __forceinline__ unsigned pack_bf16x2(float lo, float hi) {
    unsigned r;
    asm("cvt.rn.bf16x2.f32 %0, %1, %2;" : "=r"(r) : "f"(hi), "f"(lo));
    return r;
}

__device__ __forceinline__ void mma_tf32(float* c, const unsigned* a,
                                         const unsigned* b) {
    asm volatile(
        "mma.sync.aligned.m16n8k8.row.col.f32.tf32.tf32.f32 "
        "{%0,%1,%2,%3}, {%4,%5,%6,%7}, {%8,%9}, {%0,%1,%2,%3};"
        : "+f"(c[0]), "+f"(c[1]), "+f"(c[2]), "+f"(c[3])
        : "r"(a[0]), "r"(a[1]), "r"(a[2]), "r"(a[3]),
          "r"(b[0]), "r"(b[1]));
}

__device__ __forceinline__ void mma_bf16(float* c, const unsigned* a,
                                         const unsigned* b) {
    asm volatile(
        "mma.sync.aligned.m16n8k16.row.col.f32.bf16.bf16.f32 "
        "{%0,%1,%2,%3}, {%4,%5,%6,%7}, {%8,%9}, {%0,%1,%2,%3};"
        : "+f"(c[0]), "+f"(c[1]), "+f"(c[2]), "+f"(c[3])
        : "r"(a[0]), "r"(a[1]), "r"(a[2]), "r"(a[3]),
          "r"(b[0]), "r"(b[1]));
}

// ---------------------------------------------------------------------------
// setup: all preprocessing in one launch.  grid SU_F blocks x 256.
// ---------------------------------------------------------------------------
__global__ void __launch_bounds__(256) setup_kernel(
    const float* __restrict__ x,
    const float* __restrict__ t_w1, const float* __restrict__ f_w1,
    const float* __restrict__ t_w2, const float* __restrict__ f_w2)
{
    int blk = blockIdx.x;
    int tid = threadIdx.x;

    if (blk < SU_A) {
        int img = blk / 225, row = blk - img * 225;
        int col = tid;
        if (col < 224) {
            #pragma unroll
            for (int c = 0; c < 3; c++) {
                size_t base = (size_t)img * XIMG_STRIDE + c * XCH_STRIDE
                            + row * 226;
                if (row == 224) {
                    g_xp[base + col] = 0.f;
                    if (col < 2) g_xp[base + 224 + col] = 0.f;
                } else {
                    g_xp[base + (col & 1) * 113 + (col >> 1)] =
                        x[((img * 3 + c) * 224 + row) * 224 + col];
                    if (col >= 222)
                        g_xp[base + (col & 1) * 113 + 112] = 0.f;
                }
            }
        }
    } else if (blk < SU_B) {
        int i = (blk - SU_A) * 256 + tid;
        if (i < GUARD_ROW_TOTAL) {
            int ch = i / 114, slot = i % 114;
            g_h1[(size_t)ch * CH_STRIDE + 112 * 114 + slot] = 0.f;
        }
    } else if (blk < SU_C) {
        int i = (blk - SU_B) * 256 + tid;
        if (i < 2 * NB * 128) g_gap[i] = 0.f;
    } else if (blk < SU_D) {
        int i = (blk - SU_C) * 256 + tid;
        if (i < 576) {
            int ch = i / 9, t9 = i % 9, r = t9 / 3, s = t9 % 3;
            g_imoff[i] = ch * CH_STRIDE + r * 114 + (s & 1) * 57 + (s >> 1);
        }
        if (i >= 576 && i < 608) {
            int k = i - 576;
            if (k < 27) {
                int ch = k / 9, t9 = k % 9, r = t9 / 3, s = t9 % 3;
                g_xoff[k] = ch * XCH_STRIDE + r * 226 + (s & 1) * 113 + (s >> 1);
            } else {
                g_xoff[k] = 0;
            }
        }
    } else if (blk < SU_E) {
        int idx = (blk - SU_D) * 256 + tid;
        if (idx < 2 * 4 * 4 * 32) {
            int lane = idx & 31;
            int t = idx >> 5;
            int tile = t & 3;  t >>= 2;
            int ks = t & 3;    t >>= 2;
            int expert = t;
            const float* w = expert ? f_w1 : t_w1;
            int g = lane >> 2, tig = lane & 3;
            int oc0 = tile * 16 + g;
            int k0 = ks * 8 + tig;
            float a = (k0     < 27) ? w[oc0 * 27 + k0]           : 0.f;
            float b = (k0     < 27) ? w[(oc0 + 8) * 27 + k0]     : 0.f;
            float cc = (k0 + 4 < 27) ? w[oc0 * 27 + k0 + 4]      : 0.f;
            float d = (k0 + 4 < 27) ? w[(oc0 + 8) * 27 + k0 + 4] : 0.f;
            float4 hv = make_float4(
                __uint_as_float(f2tf(a)), __uint_as_float(f2tf(b)),
                __uint_as_float(f2tf(cc)), __uint_as_float(f2tf(d)));
            *(float4*)&g_w1f[(size_t)idx * 4] = hv;
        }
    } else {
        int idx = (blk - SU_E) * 256 + tid;
        if (idx < 2 * 18 * 2 * 8 * 32) {
            int lane = idx & 31;
            int t = idx >> 5;
            int tile = t & 7;  t >>= 3;
            int s = t & 1;     t >>= 1;
            int q = t % 18;
            int expert = t / 18;
            const float* w = expert ? f_w2 : t_w2;
            int g = lane >> 2, tig = lane & 3;
            int r0 = tile * 16 + g, r1 = r0 + 8;
            int kb = q * 32 + s * 16 + tig * 2;

            float wv[4][2] = {
                { w[r0 * 576 + kb],     w[r0 * 576 + kb + 1] },
                { w[r1 * 576 + kb],     w[r1 * 576 + kb + 1] },
                { w[r0 * 576 + kb + 8], w[r0 * 576 + kb + 9] },
                { w[r1 * 576 + kb + 8], w[r1 * 576 + kb + 9] } };

            unsigned ah[4], al[4];
            #pragma unroll
            for (int a4 = 0; a4 < 4; a4++) {
                float h0 = __bfloat162float(__float2bfloat16_rn(wv[a4][0]));
                float h1 = __bfloat162float(__float2bfloat16_rn(wv[a4][1]));
                ah[a4] = pack_bf16x2(h0, h1);
                al[a4] = pack_bf16x2(wv[a4][0] - h0, wv[a4][1] - h1);
            }
            float* dst = &g_w2f[(size_t)expert * WFRAG_PER_EXPERT
                                + (size_t)(idx % (18 * 2 * 8 * 32)) * 8];
            *(float4*)dst = make_float4(
                __uint_as_float(ah[0]), __uint_as_float(ah[1]),
                __uint_as_float(ah[2]), __uint_as_float(ah[3]));
            *(float4*)(dst + 4) = make_float4(
                __uint_as_float(al[0]), __uint_as_float(al[1]),
                __uint_as_float(al[2]), __uint_as_float(al[3]));
        }
    }
}

// ---------------------------------------------------------------------------
// conv1 via mma.sync tf32 (R13 winner, unchanged).
// grid: (112 rows, 64 images, 2 experts), block 128.
// ---------------------------------------------------------------------------
#define PADX 120

__global__ void __launch_bounds__(128, 4) conv1_mma_kernel(
    const float* __restrict__ t_b1, const float* __restrict__ f_b1)
{
    __shared__ __align__(16) float smem[64 * 114];
    float2* sB = (float2*)smem;

    int tid = threadIdx.x;
    int wid = tid >> 5, lane = tid & 31;
    int g = lane >> 2, tig = lane & 3;
    int warpM = wid >> 1, warpN = wid & 1;

    int expert = blockIdx.z;
    int img = blockIdx.y;
    int y = blockIdx.x;

    const float* rbase = g_xp + (size_t)img * XIMG_STRIDE + (size_t)y * 452;
    const float* wfrag = g_w1f + (size_t)expert * W1FRAG_PER_EXPERT + lane * 4;
    const float* bs = expert ? f_b1 : t_b1;

    #pragma unroll
    for (int j = 0; j < 14; j++) {
        int i = j * 128 + tid;
        int pair = i / 112, px = i - pair * 112;
        int k0 = (pair >> 2) * 8 + (pair & 3);
        unsigned e0 = __ldg(&g_xoff[k0]);
        unsigned e1 = __ldg(&g_xoff[k0 + 4]);
        float v0 = rbase[e0 + px];
        float v1 = rbase[e1 + px];
        sB[pair * PADX + px] = make_float2(__uint_as_float(f2tf(v0)),
                                           __uint_as_float(f2tf(v1)));
    }
    __syncthreads();

    float acc[2][7][4];
    #pragma unroll
    for (int mt = 0; mt < 2; mt++)
        #pragma unroll
        for (int nt = 0; nt < 7; nt++)
            #pragma unroll
            for (int i = 0; i < 4; i++) acc[mt][nt][i] = 0.f;

    #pragma unroll
    for (int ks = 0; ks < 4; ks++) {
        float2 bp[7];
        #pragma unroll
        for (int nt = 0; nt < 7; nt++)
            bp[nt] = sB[(ks * 4 + tig) * PADX + warpN * 56 + nt * 8 + g];
        #pragma unroll
        for (int mt = 0; mt < 2; mt++) {
            float4 hv = __ldg((const float4*)(wfrag
                        + (size_t)((ks * 4) + warpM * 2 + mt) * 128));
            unsigned ah[4] = {__float_as_uint(hv.x), __float_as_uint(hv.y),
                              __float_as_uint(hv.z), __float_as_uint(hv.w)};
            #pragma unroll
            for (int nt = 0; nt < 7; nt++) {
                unsigned bfr[2] = {__float_as_uint(bp[nt].x),
                                   __float_as_uint(bp[nt].y)};
                mma_tf32(acc[mt][nt], ah, bfr);
            }
        }
    }
    __syncthreads();

    #pragma unroll
    for (int mt = 0; mt < 2; mt++) {
        int oc0 = warpM * 32 + mt * 16 + g;
        float bv0 = __ldg(&bs[oc0]);
        float bv1 = __ldg(&bs[oc0 + 8]);
        #pragma unroll
        for (int nt = 0; nt < 7; nt++) {
            int px0 = warpN * 56 + nt * 8 + tig * 2;
            int idx = px0 >> 1;
            smem[oc0 * 114 + idx]            = fmaxf(acc[mt][nt][0] + bv0, 0.f);
            smem[oc0 * 114 + 57 + idx]       = fmaxf(acc[mt][nt][1] + bv0, 0.f);
            smem[(oc0 + 8) * 114 + idx]      = fmaxf(acc[mt][nt][2] + bv1, 0.f);
            smem[(oc0 + 8) * 114 + 57 + idx] = fmaxf(acc[mt][nt][3] + bv1, 0.f);
        }
    }
    __syncthreads();

    float2* sD = (float2*)smem;
    float2* h1o2 = (float2*)(g_h1 + expert * EXPP + (size_t)img * IMG_STRIDE
                             + (size_t)y * 114);
    int oc = (tid >= 114) ? 2 : (tid >= 57 ? 1 : 0);
    int c2 = tid - oc * 57;
    #pragma unroll 4
    for (int it = 0; it < 28; it++) {
        float2 v = sD[oc * 57 + c2];
        if (c2 == 28) v.x = 0.f;
        if (c2 == 56) v.y = 0.f;
        h1o2[oc * 6441 + c2] = v;
        c2 += 14; oc += 2;
        if (c2 >= 57) { c2 -= 57; oc++; }
    }
    if (tid < 64) {
        float2 v = sD[oc * 57 + c2];
        if (c2 == 28) v.x = 0.f;
        if (c2 == 56) v.y = 0.f;
        h1o2[oc * 6441 + c2] = v;
    }
}

// ---------------------------------------------------------------------------
// conv2 via mma.sync bf16 m16n8k16 (R14 winner config: occ 4, no spills).
// grid: (56 rows, 64 images, 2 experts), block 128.
// ---------------------------------------------------------------------------
#define PADB 72

__global__ void __launch_bounds__(128, 4) conv2_mma_kernel(
    const float* __restrict__ t_b2, const float* __restrict__ f_b2)
{
    __shared__ unsigned sBu[2][16 * PADB];

    int tid = threadIdx.x;
    int wid = tid >> 5, lane = tid & 31;
    int g = lane >> 2, tig = lane & 3;

    int expert = blockIdx.z;
    int img = blockIdx.y;
    int y = blockIdx.x;

    const float* rbase = g_h1 + expert * EXPP + (size_t)img * IMG_STRIDE
                       + (size_t)y * 228;
    const float* wfrag = g_w2f + (size_t)expert * WFRAG_PER_EXPERT
                       + (size_t)(wid * 2) * 256 + lane * 8;
    const float* bs = expert ? f_b2 : t_b2;

    float acc[2][7][4];
    #pragma unroll
    for (int mt = 0; mt < 2; mt++)
        #pragma unroll
        for (int nt = 0; nt < 7; nt++)
            #pragma unroll
            for (int i = 0; i < 4; i++) acc[mt][nt][i] = 0.f;

    // packed gather geometry: geom[j] = (kp << 16) | px
    unsigned geom[7];
    #pragma unroll
    for (int j = 0; j < 7; j++) {
        int w = j * 128 + tid;
        int kp = w / 56, px = w - kp * 56;
        geom[j] = ((unsigned)kp << 16) | (unsigned)px;
    }

    float v0[7], v1[7];
    auto load_chunk = [&](int kb) {
        #pragma unroll
        for (int j = 0; j < 7; j++) {
            int kp = geom[j] >> 16, px = geom[j] & 0xFFFF;
            unsigned e0 = __ldg(&g_imoff[kb + kp * 2]);
            unsigned e1 = __ldg(&g_imoff[kb + kp * 2 + 1]);
            v0[j] = rbase[e0 + px];
            v1[j] = rbase[e1 + px];
        }
    };

    load_chunk(0);

    for (int q = 0; q < 18; q++) {
        int buf = q & 1;
        #pragma unroll
        for (int j = 0; j < 7; j++) {
            int kp = geom[j] >> 16, px = geom[j] & 0xFFFF;
            sBu[buf][kp * PADB + px] = pack_bf16x2(v0[j], v1[j]);
        }
        __syncthreads();
        if (q < 17) load_chunk((q + 1) * 32);

        const float* ap = wfrag + (size_t)q * 4096;
        #pragma unroll
        for (int s = 0; s < 2; s++) {
            unsigned ah[2][4], al[2][4];
            #pragma unroll
            for (int mt = 0; mt < 2; mt++) {
                float4 hv = __ldg((const float4*)(ap + s * 2048 + mt * 256));
                float4 lv = __ldg((const float4*)(ap + s * 2048 + mt * 256 + 4));
                ah[mt][0] = __float_as_uint(hv.x); ah[mt][1] = __float_as_uint(hv.y);
                ah[mt][2] = __float_as_uint(hv.z); ah[mt][3] = __float_as_uint(hv.w);
                al[mt][0] = __float_as_uint(lv.x); al[mt][1] = __float_as_uint(lv.y);
                al[mt][2] = __float_as_uint(lv.z); al[mt][3] = __float_as_uint(lv.w);
            }
            const unsigned* rb0 = &sBu[buf][(s * 8 + tig) * PADB];
            const unsigned* rb1 = rb0 + 4 * PADB;
            #pragma unroll
            for (int nt = 0; nt < 7; nt++) {
                int px = nt * 8 + g;
                unsigned bb[2] = { rb0[px], rb1[px] };
                #pragma unroll
                for (int mt = 0; mt < 2; mt++) {
                    mma_bf16(acc[mt][nt], ah[mt], bb);
                    mma_bf16(acc[mt][nt], al[mt], bb);
                }
            }
        }
    }

    float* gap = &g_gap[expert * (NB * 128) + img * 128];
    #pragma unroll
    for (int mt = 0; mt < 2; mt++) {
        int oc0 = wid * 32 + mt * 16 + g;
        float bv0 = __ldg(&bs[oc0]);
        float bv1 = __ldg(&bs[oc0 + 8]);
        float s0 = 0.f, s1 = 0.f;
        #pragma unroll
        for (int nt = 0; nt < 7; nt++) {
            s0 += fmaxf(acc[mt][nt][0] + bv0, 0.f) + fmaxf(acc[mt][nt][1] + bv0, 0.f);
            s1 += fmaxf(acc[mt][nt][2] + bv1, 0.f) + fmaxf(acc[mt][nt][3] + bv1, 0.f);
        }
        s0 += __shfl_xor_sync(0xffffffffu, s0, 1);
        s0 += __shfl_xor_sync(0xffffffffu, s0, 2);
        s1 += __shfl_xor_sync(0xffffffffu, s1, 1);
        s1 += __shfl_xor_sync(0xffffffffu, s1, 2);
        if (tig == 0) {
            atomicAdd(&gap[oc0], s0);
            atomicAdd(&gap[oc0 + 8], s1);
        }
    }
}

// ---------------------------------------------------------------------------
// final: 512 threads; thread (b, octet) sums 16 k each, shuffle-reduce.
// ---------------------------------------------------------------------------
__global__ void final_kernel(const float* __restrict__ t_wf,
                             const float* __restrict__ t_bf,
                             const float* __restrict__ f_wf,
                             const float* __restrict__ f_bf,
                             float* __restrict__ out)
{
    __shared__ int cnt[NB];
    int t = threadIdx.x;
    int b = t >> 3, oc = t & 7;

    float tl0 = 0.f, tl1 = 0.f, fl0 = 0.f, fl1 = 0.f;
    const float inv = 1.0f / 3136.0f;
    #pragma unroll
    for (int kk = 0; kk < 16; kk++) {
        int k = oc * 16 + kk;
        float gt = g_gap[b * 128 + k] * inv;
        float gf = g_gap[NB * 128 + b * 128 + k] * inv;
        tl0 = fmaf(gt, t_wf[2 * k], tl0);
        tl1 = fmaf(gt, t_wf[2 * k + 1], tl1);
        fl0 = fmaf(gf, f_wf[2 * k], fl0);
        fl1 = fmaf(gf, f_wf[2 * k + 1], fl1);
    }
    #pragma unroll
    for (int off = 1; off <= 4; off <<= 1) {
        tl0 += __shfl_xor_sync(0xffffffffu, tl0, off);
        tl1 += __shfl_xor_sync(0xffffffffu, tl1, off);
        fl0 += __shfl_xor_sync(0xffffffffu, fl0, off);
        fl1 += __shfl_xor_sync(0xffffffffu, fl1, off);
    }
    if (oc == 0) {
        tl0 += t_bf[0]; tl1 += t_bf[1];
        fl0 += f_bf[0]; fl1 += f_bf[1];
        int m = (fabsf(tl0 - tl1) <= 2.1972245773362196f) ? 1 : 0;
        out[2 * b]     = m ? (0.7f * tl0 + 0.3f * fl0) : tl0;
        out[2 * b + 1] = m ? (0.7f * tl1 + 0.3f * fl1) : tl1;
        cnt[b] = m;
    }
    __syncthreads();
    if (t == 0) {
        int c = 0;
        for (int i = 0; i < NB; i++) c += cnt[i];
        out[128] = (float)c / (float)NB;
    }
}

extern "C" void kernel_launch(void* const* d_in, const int* in_sizes, int n_in,
                              void* d_out, int out_size)
{
    const float* x    = (const float*)d_in[0];
    const float* t_w1 = (const float*)d_in[1];
    const float* t_b1 = (const float*)d_in[2];
    const float* t_w2 = (const float*)d_in[3];
    const float* t_b2 = (const float*)d_in[4];
    const float* t_wf = (const float*)d_in[5];
    const float* t_bf = (const float*)d_in[6];
    const float* f_w1 = (const float*)d_in[7];
    const float* f_b1 = (const float*)d_in[8];
    const float* f_w2 = (const float*)d_in[9];
    const float* f_b2 = (const float*)d_in[10];
    const float* f_wf = (const float*)d_in[11];
    const float* f_bf = (const float*)d_in[12];
    float* out = (float*)d_out;

    setup_kernel<<<SU_F, 256>>>(x, t_w1, f_w1, t_w2, f_w2);
    conv1_mma_kernel<<<dim3(112, 64, 2), 128>>>(t_b1, f_b1);
    conv2_mma_kernel<<<dim3(56, 64, 2), 128>>>(t_b2, f_b2);
    final_kernel<<<1, 512>>>(t_wf, t_bf, f_wf, f_bf, out);
}

// round 17
// speedup vs baseline: 1.3072x; 1.0384x over previous
#include <cuda_runtime.h>
#include <cuda_bf16.h>

// ---------------------------------------------------------------------------
// AdaptiveSystem: 2-expert CNN MoE.
// setup (1 kernel): relayout x->xp, h1 guard rows, gap zero, tables,
//     w1 (tf32) / w2 (bf16 hi+lo split) fragment prep.
// conv1 (3->64)  : mma.sync tf32 m16n8k8, K=32 (27+5 pad).
// conv2 (64->128): mma.sync bf16 m16n8k16, A = w_hi+w_lo bf16 split,
//     B = single-bf16 activations; warp = 32oc x 56px; fused GAP.
//     R17: exact R14 conv2 (unpacked geometry arrays, occ 4 — the packed
//     geometry of R15/R16 added hot-loop ALU for nothing at occ 4).
// gate: softmax-max <= 0.9  <=>  |l0-l1| <= ln(9)
// ---------------------------------------------------------------------------

#define NB 64
#define CH_STRIDE 12882                 // h1: 113 * 114
#define IMG_STRIDE ((size_t)64 * CH_STRIDE)
#define EXPP ((size_t)NB * IMG_STRIDE)

#define XCH_STRIDE 50850                // xp: 225 * 226
#define XIMG_STRIDE (3 * XCH_STRIDE)

#define WFRAG_PER_EXPERT (18 * 2 * 8 * 32 * 8)   // bf16 frags
#define W1FRAG_PER_EXPERT (4 * 4 * 32 * 4)
#define GUARD_ROW_TOTAL (2 * NB * 64 * 114)

// setup kernel block ranges
#define SU_A 14400
#define SU_B (SU_A + 3648)
#define SU_C (SU_B + 64)
#define SU_D (SU_C + 3)
#define SU_E (SU_D + 4)
#define SU_F (SU_E + 72)

__device__ float g_h1[2 * EXPP];
__device__ float g_xp[(size_t)NB * XIMG_STRIDE];
__device__ __align__(16) float g_w2f[2 * WFRAG_PER_EXPERT];
__device__ __align__(16) float g_w1f[2 * W1FRAG_PER_EXPERT];
__device__ unsigned g_imoff[576];
__device__ unsigned g_xoff[32];
__device__ float g_gap[2 * NB * 128];

__device__ __forceinline__ unsigned f2tf(float v) {
    unsigned r;
    asm("cvt.rna.tf32.f32 %0, %1;" : "=r"(r) : "f"(v));
    return r;
}

__device__ __forceinline__ unsigned pack_bf16x2(float lo, float hi) {
    unsigned r;
    asm("cvt.rn.bf16x2.f32 %0, %1, %2;" : "=r"(r) : "f"(hi), "f"(lo));
    return r;
}

__device__ __forceinline__ void mma_tf32(float* c, const unsigned* a,
                                         const unsigned* b) {
    asm volatile(
        "mma.sync.aligned.m16n8k8.row.col.f32.tf32.tf32.f32 "
        "{%0,%1,%2,%3}, {%4,%5,%6,%7}, {%8,%9}, {%0,%1,%2,%3};"
        : "+f"(c[0]), "+f"(c[1]), "+f"(c[2]), "+f"(c[3])
        : "r"(a[0]), "r"(a[1]), "r"(a[2]), "r"(a[3]),
          "r"(b[0]), "r"(b[1]));
}

__device__ __forceinline__ void mma_bf16(float* c, const unsigned* a,
                                         const unsigned* b) {
    asm volatile(
        "mma.sync.aligned.m16n8k16.row.col.f32.bf16.bf16.f32 "
        "{%0,%1,%2,%3}, {%4,%5,%6,%7}, {%8,%9}, {%0,%1,%2,%3};"
        : "+f"(c[0]), "+f"(c[1]), "+f"(c[2]), "+f"(c[3])
        : "r"(a[0]), "r"(a[1]), "r"(a[2]), "r"(a[3]),
          "r"(b[0]), "r"(b[1]));
}

// ---------------------------------------------------------------------------
// setup: all preprocessing in one launch.  grid SU_F blocks x 256.
// ---------------------------------------------------------------------------
__global__ void __launch_bounds__(256) setup_kernel(
    const float* __restrict__ x,
    const float* __restrict__ t_w1, const float* __restrict__ f_w1,
    const float* __restrict__ t_w2, const float* __restrict__ f_w2)
{
    int blk = blockIdx.x;
    int tid = threadIdx.x;

    if (blk < SU_A) {
        int img = blk / 225, row = blk - img * 225;
        int col = tid;
        if (col < 224) {
            #pragma unroll
            for (int c = 0; c < 3; c++) {
                size_t base = (size_t)img * XIMG_STRIDE + c * XCH_STRIDE
                            + row * 226;
                if (row == 224) {
                    g_xp[base + col] = 0.f;
                    if (col < 2) g_xp[base + 224 + col] = 0.f;
                } else {
                    g_xp[base + (col & 1) * 113 + (col >> 1)] =
                        x[((img * 3 + c) * 224 + row) * 224 + col];
                    if (col >= 222)
                        g_xp[base + (col & 1) * 113 + 112] = 0.f;
                }
            }
        }
    } else if (blk < SU_B) {
        int i = (blk - SU_A) * 256 + tid;
        if (i < GUARD_ROW_TOTAL) {
            int ch = i / 114, slot = i % 114;
            g_h1[(size_t)ch * CH_STRIDE + 112 * 114 + slot] = 0.f;
        }
    } else if (blk < SU_C) {
        int i = (blk - SU_B) * 256 + tid;
        if (i < 2 * NB * 128) g_gap[i] = 0.f;
    } else if (blk < SU_D) {
        int i = (blk - SU_C) * 256 + tid;
        if (i < 576) {
            int ch = i / 9, t9 = i % 9, r = t9 / 3, s = t9 % 3;
            g_imoff[i] = ch * CH_STRIDE + r * 114 + (s & 1) * 57 + (s >> 1);
        }
        if (i >= 576 && i < 608) {
            int k = i - 576;
            if (k < 27) {
                int ch = k / 9, t9 = k % 9, r = t9 / 3, s = t9 % 3;
                g_xoff[k] = ch * XCH_STRIDE + r * 226 + (s & 1) * 113 + (s >> 1);
            } else {
                g_xoff[k] = 0;
            }
        }
    } else if (blk < SU_E) {
        int idx = (blk - SU_D) * 256 + tid;
        if (idx < 2 * 4 * 4 * 32) {
            int lane = idx & 31;
            int t = idx >> 5;
            int tile = t & 3;  t >>= 2;
            int ks = t & 3;    t >>= 2;
            int expert = t;
            const float* w = expert ? f_w1 : t_w1;
            int g = lane >> 2, tig = lane & 3;
            int oc0 = tile * 16 + g;
            int k0 = ks * 8 + tig;
            float a = (k0     < 27) ? w[oc0 * 27 + k0]           : 0.f;
            float b = (k0     < 27) ? w[(oc0 + 8) * 27 + k0]     : 0.f;
            float cc = (k0 + 4 < 27) ? w[oc0 * 27 + k0 + 4]      : 0.f;
            float d = (k0 + 4 < 27) ? w[(oc0 + 8) * 27 + k0 + 4] : 0.f;
            float4 hv = make_float4(
                __uint_as_float(f2tf(a)), __uint_as_float(f2tf(b)),
                __uint_as_float(f2tf(cc)), __uint_as_float(f2tf(d)));
            *(float4*)&g_w1f[(size_t)idx * 4] = hv;
        }
    } else {
        int idx = (blk - SU_E) * 256 + tid;
        if (idx < 2 * 18 * 2 * 8 * 32) {
            int lane = idx & 31;
            int t = idx >> 5;
            int tile = t & 7;  t >>= 3;
            int s = t & 1;     t >>= 1;
            int q = t % 18;
            int expert = t / 18;
            const float* w = expert ? f_w2 : t_w2;
            int g = lane >> 2, tig = lane & 3;
            int r0 = tile * 16 + g, r1 = r0 + 8;
            int kb = q * 32 + s * 16 + tig * 2;

            float wv[4][2] = {
                { w[r0 * 576 + kb],     w[r0 * 576 + kb + 1] },
                { w[r1 * 576 + kb],     w[r1 * 576 + kb + 1] },
                { w[r0 * 576 + kb + 8], w[r0 * 576 + kb + 9] },
                { w[r1 * 576 + kb + 8], w[r1 * 576 + kb + 9] } };

            unsigned ah[4], al[4];
            #pragma unroll
            for (int a4 = 0; a4 < 4; a4++) {
                float h0 = __bfloat162float(__float2bfloat16_rn(wv[a4][0]));
                float h1 = __bfloat162float(__float2bfloat16_rn(wv[a4][1]));
                ah[a4] = pack_bf16x2(h0, h1);
                al[a4] = pack_bf16x2(wv[a4][0] - h0, wv[a4][1] - h1);
            }
            float* dst = &g_w2f[(size_t)expert * WFRAG_PER_EXPERT
                                + (size_t)(idx % (18 * 2 * 8 * 32)) * 8];
            *(float4*)dst = make_float4(
                __uint_as_float(ah[0]), __uint_as_float(ah[1]),
                __uint_as_float(ah[2]), __uint_as_float(ah[3]));
            *(float4*)(dst + 4) = make_float4(
                __uint_as_float(al[0]), __uint_as_float(al[1]),
                __uint_as_float(al[2]), __uint_as_float(al[3]));
        }
    }
}

// ---------------------------------------------------------------------------
// conv1 via mma.sync tf32 (R13 winner, unchanged).
// grid: (112 rows, 64 images, 2 experts), block 128.
// ---------------------------------------------------------------------------
#define PADX 120

__global__ void __launch_bounds__(128, 4) conv1_mma_kernel(
    const float* __restrict__ t_b1, const float* __restrict__ f_b1)
{
    __shared__ __align__(16) float smem[64 * 114];
    float2* sB = (float2*)smem;

    int tid = threadIdx.x;
    int wid = tid >> 5, lane = tid & 31;
    int g = lane >> 2, tig = lane & 3;
    int warpM = wid >> 1, warpN = wid & 1;

    int expert = blockIdx.z;
    int img = blockIdx.y;
    int y = blockIdx.x;

    const float* rbase = g_xp + (size_t)img * XIMG_STRIDE + (size_t)y * 452;
    const float* wfrag = g_w1f + (size_t)expert * W1FRAG_PER_EXPERT + lane * 4;
    const float* bs = expert ? f_b1 : t_b1;

    #pragma unroll
    for (int j = 0; j < 14; j++) {
        int i = j * 128 + tid;
        int pair = i / 112, px = i - pair * 112;
        int k0 = (pair >> 2) * 8 + (pair & 3);
        unsigned e0 = __ldg(&g_xoff[k0]);
        unsigned e1 = __ldg(&g_xoff[k0 + 4]);
        float v0 = rbase[e0 + px];
        float v1 = rbase[e1 + px];
        sB[pair * PADX + px] = make_float2(__uint_as_float(f2tf(v0)),
                                           __uint_as_float(f2tf(v1)));
    }
    __syncthreads();

    float acc[2][7][4];
    #pragma unroll
    for (int mt = 0; mt < 2; mt++)
        #pragma unroll
        for (int nt = 0; nt < 7; nt++)
            #pragma unroll
            for (int i = 0; i < 4; i++) acc[mt][nt][i] = 0.f;

    #pragma unroll
    for (int ks = 0; ks < 4; ks++) {
        float2 bp[7];
        #pragma unroll
        for (int nt = 0; nt < 7; nt++)
            bp[nt] = sB[(ks * 4 + tig) * PADX + warpN * 56 + nt * 8 + g];
        #pragma unroll
        for (int mt = 0; mt < 2; mt++) {
            float4 hv = __ldg((const float4*)(wfrag
                        + (size_t)((ks * 4) + warpM * 2 + mt) * 128));
            unsigned ah[4] = {__float_as_uint(hv.x), __float_as_uint(hv.y),
                              __float_as_uint(hv.z), __float_as_uint(hv.w)};
            #pragma unroll
            for (int nt = 0; nt < 7; nt++) {
                unsigned bfr[2] = {__float_as_uint(bp[nt].x),
                                   __float_as_uint(bp[nt].y)};
                mma_tf32(acc[mt][nt], ah, bfr);
            }
        }
    }
    __syncthreads();

    #pragma unroll
    for (int mt = 0; mt < 2; mt++) {
        int oc0 = warpM * 32 + mt * 16 + g;
        float bv0 = __ldg(&bs[oc0]);
        float bv1 = __ldg(&bs[oc0 + 8]);
        #pragma unroll
        for (int nt = 0; nt < 7; nt++) {
            int px0 = warpN * 56 + nt * 8 + tig * 2;
            int idx = px0 >> 1;
            smem[oc0 * 114 + idx]            = fmaxf(acc[mt][nt][0] + bv0, 0.f);
            smem[oc0 * 114 + 57 + idx]       = fmaxf(acc[mt][nt][1] + bv0, 0.f);
            smem[(oc0 + 8) * 114 + idx]      = fmaxf(acc[mt][nt][2] + bv1, 0.f);
            smem[(oc0 + 8) * 114 + 57 + idx] = fmaxf(acc[mt][nt][3] + bv1, 0.f);
        }
    }
    __syncthreads();

    float2* sD = (float2*)smem;
    float2* h1o2 = (float2*)(g_h1 + expert * EXPP + (size_t)img * IMG_STRIDE
                             + (size_t)y * 114);
    int oc = (tid >= 114) ? 2 : (tid >= 57 ? 1 : 0);
    int c2 = tid - oc * 57;
    #pragma unroll 4
    for (int it = 0; it < 28; it++) {
        float2 v = sD[oc * 57 + c2];
        if (c2 == 28) v.x = 0.f;
        if (c2 == 56) v.y = 0.f;
        h1o2[oc * 6441 + c2] = v;
        c2 += 14; oc += 2;
        if (c2 >= 57) { c2 -= 57; oc++; }
    }
    if (tid < 64) {
        float2 v = sD[oc * 57 + c2];
        if (c2 == 28) v.x = 0.f;
        if (c2 == 56) v.y = 0.f;
        h1o2[oc * 6441 + c2] = v;
    }
}

// ---------------------------------------------------------------------------
// conv2 via mma.sync bf16 m16n8k16 (exact R14 winner: unpacked geometry,
// occ 4, no spills).  grid: (56 rows, 64 images, 2 experts), block 128.
// ---------------------------------------------------------------------------
#define PADB 72

__global__ void __launch_bounds__(128, 4) conv2_mma_kernel(
    const float* __restrict__ t_b2, const float* __restrict__ f_b2)
{
    __shared__ unsigned sBu[2][16 * PADB];   // bf16x2 per entry

    int tid = threadIdx.x;
    int wid = tid >> 5, lane = tid & 31;
    int g = lane >> 2, tig = lane & 3;

    int expert = blockIdx.z;
    int img = blockIdx.y;
    int y = blockIdx.x;

    const float* rbase = g_h1 + expert * EXPP + (size_t)img * IMG_STRIDE
                       + (size_t)y * 228;
    const float* wfrag = g_w2f + (size_t)expert * WFRAG_PER_EXPERT
                       + (size_t)(wid * 2) * 256 + lane * 8;
    const float* bs = expert ? f_b2 : t_b2;

    float acc[2][7][4];
    #pragma unroll
    for (int mt = 0; mt < 2; mt++)
        #pragma unroll
        for (int nt = 0; nt < 7; nt++)
            #pragma unroll
            for (int i = 0; i < 4; i++) acc[mt][nt][i] = 0.f;

    // gather geometry: 896 items = 16 kpairs x 56 px = 7 iters x 128 thr
    int kk0[7], smix[7], pxj[7];
    #pragma unroll
    for (int j = 0; j < 7; j++) {
        int w = j * 128 + tid;
        int kp = w / 56, px = w - kp * 56;
        kk0[j] = kp * 2;                 // even k within chunk
        smix[j] = kp * PADB + px;
        pxj[j] = px;
    }

    float v0[7], v1[7];
    auto load_chunk = [&](int kb) {
        #pragma unroll
        for (int j = 0; j < 7; j++) {
            unsigned e0 = __ldg(&g_imoff[kb + kk0[j]]);
            unsigned e1 = __ldg(&g_imoff[kb + kk0[j] + 1]);
            v0[j] = rbase[e0 + pxj[j]];
            v1[j] = rbase[e1 + pxj[j]];
        }
    };

    load_chunk(0);

    for (int q = 0; q < 18; q++) {
        int buf = q & 1;
        #pragma unroll
        for (int j = 0; j < 7; j++)
            sBu[buf][smix[j]] = pack_bf16x2(v0[j], v1[j]);
        __syncthreads();
        if (q < 17) load_chunk((q + 1) * 32);

        const float* ap = wfrag + (size_t)q * 4096;
        #pragma unroll
        for (int s = 0; s < 2; s++) {
            unsigned ah[2][4], al[2][4];
            #pragma unroll
            for (int mt = 0; mt < 2; mt++) {
                float4 hv = __ldg((const float4*)(ap + s * 2048 + mt * 256));
                float4 lv = __ldg((const float4*)(ap + s * 2048 + mt * 256 + 4));
                ah[mt][0] = __float_as_uint(hv.x); ah[mt][1] = __float_as_uint(hv.y);
                ah[mt][2] = __float_as_uint(hv.z); ah[mt][3] = __float_as_uint(hv.w);
                al[mt][0] = __float_as_uint(lv.x); al[mt][1] = __float_as_uint(lv.y);
                al[mt][2] = __float_as_uint(lv.z); al[mt][3] = __float_as_uint(lv.w);
            }
            const unsigned* rb0 = &sBu[buf][(s * 8 + tig) * PADB];
            const unsigned* rb1 = rb0 + 4 * PADB;
            #pragma unroll
            for (int nt = 0; nt < 7; nt++) {
                int px = nt * 8 + g;
                unsigned bb[2] = { rb0[px], rb1[px] };
                #pragma unroll
                for (int mt = 0; mt < 2; mt++) {
                    mma_bf16(acc[mt][nt], ah[mt], bb);
                    mma_bf16(acc[mt][nt], al[mt], bb);
                }
            }
        }
    }

    float* gap = &g_gap[expert * (NB * 128) + img * 128];
    #pragma unroll
    for (int mt = 0; mt < 2; mt++) {
        int oc0 = wid * 32 + mt * 16 + g;
        float bv0 = __ldg(&bs[oc0]);
        float bv1 = __ldg(&bs[oc0 + 8]);
        float s0 = 0.f, s1 = 0.f;
        #pragma unroll
        for (int nt = 0; nt < 7; nt++) {
            s0 += fmaxf(acc[mt][nt][0] + bv0, 0.f) + fmaxf(acc[mt][nt][1] + bv0, 0.f);
            s1 += fmaxf(acc[mt][nt][2] + bv1, 0.f) + fmaxf(acc[mt][nt][3] + bv1, 0.f);
        }
        s0 += __shfl_xor_sync(0xffffffffu, s0, 1);
        s0 += __shfl_xor_sync(0xffffffffu, s0, 2);
        s1 += __shfl_xor_sync(0xffffffffu, s1, 1);
        s1 += __shfl_xor_sync(0xffffffffu, s1, 2);
        if (tig == 0) {
            atomicAdd(&gap[oc0], s0);
            atomicAdd(&gap[oc0 + 8], s1);
        }
    }
}

// ---------------------------------------------------------------------------
// final: 512 threads; thread (b, octet) sums 16 k each, shuffle-reduce.
// ---------------------------------------------------------------------------
__global__ void final_kernel(const float* __restrict__ t_wf,
                             const float* __restrict__ t_bf,
                             const float* __restrict__ f_wf,
                             const float* __restrict__ f_bf,
                             float* __restrict__ out)
{
    __shared__ int cnt[NB];
    int t = threadIdx.x;
    int b = t >> 3, oc = t & 7;

    float tl0 = 0.f, tl1 = 0.f, fl0 = 0.f, fl1 = 0.f;
    const float inv = 1.0f / 3136.0f;
    #pragma unroll
    for (int kk = 0; kk < 16; kk++) {
        int k = oc * 16 + kk;
        float gt = g_gap[b * 128 + k] * inv;
        float gf = g_gap[NB * 128 + b * 128 + k] * inv;
        tl0 = fmaf(gt, t_wf[2 * k], tl0);
        tl1 = fmaf(gt, t_wf[2 * k + 1], tl1);
        fl0 = fmaf(gf, f_wf[2 * k], fl0);
        fl1 = fmaf(gf, f_wf[2 * k + 1], fl1);
    }
    #pragma unroll
    for (int off = 1; off <= 4; off <<= 1) {
        tl0 += __shfl_xor_sync(0xffffffffu, tl0, off);
        tl1 += __shfl_xor_sync(0xffffffffu, tl1, off);
        fl0 += __shfl_xor_sync(0xffffffffu, fl0, off);
        fl1 += __shfl_xor_sync(0xffffffffu, fl1, off);
    }
    if (oc == 0) {
        tl0 += t_bf[0]; tl1 += t_bf[1];
        fl0 += f_bf[0]; fl1 += f_bf[1];
        int m = (fabsf(tl0 - tl1) <= 2.1972245773362196f) ? 1 : 0;
        out[2 * b]     = m ? (0.7f * tl0 + 0.3f * fl0) : tl0;
        out[2 * b + 1] = m ? (0.7f * tl1 + 0.3f * fl1) : tl1;
        cnt[b] = m;
    }
    __syncthreads();
    if (t == 0) {
        int c = 0;
        for (int i = 0; i < NB; i++) c += cnt[i];
        out[128] = (float)c / (float)NB;
    }
}

extern "C" void kernel_launch(void* const* d_in, const int* in_sizes, int n_in,
                              void* d_out, int out_size)
{
    const float* x    = (const float*)d_in[0];
    const float* t_w1 = (const float*)d_in[1];
    const float* t_b1 = (const float*)d_in[2];
    const float* t_w2 = (const float*)d_in[3];
    const float* t_b2 = (const float*)d_in[4];
    const float* t_wf = (const float*)d_in[5];
    const float* t_bf = (const float*)d_in[6];
    const float* f_w1 = (const float*)d_in[7];
    const float* f_b1 = (const float*)d_in[8];
    const float* f_w2 = (const float*)d_in[9];
    const float* f_b2 = (const float*)d_in[10];
    const float* f_wf = (const float*)d_in[11];
    const float* f_bf = (const float*)d_in[12];
    float* out = (float*)d_out;

    setup_kernel<<<SU_F, 256>>>(x, t_w1, f_w1, t_w2, f_w2);
    conv1_mma_kernel<<<dim3(112, 64, 2), 128>>>(t_b1, f_b1);
    conv2_mma_kernel<<<dim3(56, 64, 2), 128>>>(t_b2, f_b2);
    final_kernel<<<1, 512>>>(t_wf, t_bf, f_wf, f_bf, out);
}